// round 1
// baseline (speedup 1.0000x reference)
#include <cuda_runtime.h>
#include <math_constants.h>

#define BB 4
#define SS 4096
#define DD 1024
#define WND 128
#define KTOP 64
#define RSTRIDE 10
#define RBUDGET 409

// scratch (no allocation allowed in kernel_launch)
__device__ float g_scores[BB * SS];
__device__ unsigned char g_flag[BB * SS];   // 1 = global-or-random token
__device__ unsigned int g_count[BB];

// ---------------------------------------------------------------------------
// 1) scores[b,s] = dot(hidden[b,s,:], W_imp); -inf where invalid
//    one warp per row, float4 loads
// ---------------------------------------------------------------------------
__global__ void scores_kernel(const float* __restrict__ h,
                              const int* __restrict__ am,
                              const float* __restrict__ w) {
    int gw = (blockIdx.x * blockDim.x + threadIdx.x) >> 5;
    int lane = threadIdx.x & 31;
    if (gw >= BB * SS) return;
    const float4* hv = reinterpret_cast<const float4*>(h + (size_t)gw * DD);
    const float4* wv = reinterpret_cast<const float4*>(w);
    float acc = 0.f;
#pragma unroll 4
    for (int i = lane; i < DD / 4; i += 32) {
        float4 a = hv[i];
        float4 b = wv[i];
        acc += a.x * b.x + a.y * b.y + a.z * b.z + a.w * b.w;
    }
#pragma unroll
    for (int o = 16; o; o >>= 1) acc += __shfl_xor_sync(0xffffffffu, acc, o);
    if (lane == 0)
        g_scores[gw] = am[gw] ? acc : -CUDART_INF_F;
}

// ---------------------------------------------------------------------------
// 2) init flags with random tokens, zero counters
// ---------------------------------------------------------------------------
__global__ void init_kernel() {
    int idx = blockIdx.x * blockDim.x + threadIdx.x;
    if (idx < BB * SS) {
        int s = idx % SS;
        g_flag[idx] = ((s % RSTRIDE) == 0 && (s / RSTRIDE) < RBUDGET) ? 1 : 0;
    }
    if (idx < BB) g_count[idx] = 0u;
}

// ---------------------------------------------------------------------------
// 3) top-64 per batch: iterative max with (value desc, index asc) tie-break,
//    matching jax.lax.top_k. One 1024-thread block per batch, scores in smem.
// ---------------------------------------------------------------------------
__global__ void topk_kernel() {
    __shared__ float sval[SS];
    __shared__ float wmax[32];
    __shared__ int widx[32];
    int b = blockIdx.x;
    int t = threadIdx.x;
    for (int i = t; i < SS; i += 1024) sval[i] = g_scores[b * SS + i];
    __syncthreads();

    for (int it = 0; it < KTOP; it++) {
        float best = -CUDART_INF_F;
        int bidx = SS;
#pragma unroll
        for (int k = 0; k < SS / 1024; k++) {
            int i = t + k * 1024;
            float v = sval[i];
            if (v > best || (v == best && i < bidx)) { best = v; bidx = i; }
        }
#pragma unroll
        for (int o = 16; o; o >>= 1) {
            float ov = __shfl_xor_sync(0xffffffffu, best, o);
            int oi = __shfl_xor_sync(0xffffffffu, bidx, o);
            if (ov > best || (ov == best && oi < bidx)) { best = ov; bidx = oi; }
        }
        if ((t & 31) == 0) { wmax[t >> 5] = best; widx[t >> 5] = bidx; }
        __syncthreads();
        if (t < 32) {
            best = wmax[t];
            bidx = widx[t];
#pragma unroll
            for (int o = 16; o; o >>= 1) {
                float ov = __shfl_xor_sync(0xffffffffu, best, o);
                int oi = __shfl_xor_sync(0xffffffffu, bidx, o);
                if (ov > best || (ov == best && oi < bidx)) { best = ov; bidx = oi; }
            }
            if (t == 0) {
                g_flag[b * SS + bidx] = 1;
                sval[bidx] = -CUDART_INF_F;
            }
        }
        __syncthreads();
    }
}

// ---------------------------------------------------------------------------
// 4) mask write + per-batch connection count
//    mask[b,i,j] = valid_i & valid_j & (j<=i) & (i-j<WND | flag_i | flag_j)
//    one 256-thread block per (row i, batch b); float4 stores
// ---------------------------------------------------------------------------
__global__ void mask_kernel(const int* __restrict__ am,
                            float* __restrict__ out) {
    int i = blockIdx.x;
    int b = blockIdx.y;
    int t = threadIdx.x;
    const unsigned char* flag = g_flag + b * SS;
    const int* amb = am + b * SS;
    bool validi = amb[i] != 0;
    bool rowAll = flag[i] != 0;
    float4* orow = reinterpret_cast<float4*>(out + ((size_t)b * SS + i) * SS);
    unsigned int cnt = 0;

#pragma unroll
    for (int q = 0; q < 4; q++) {
        int v4 = t + q * 256;     // float4 index within the row
        int j0 = v4 * 4;
        float4 r;
        float* rp = reinterpret_cast<float*>(&r);
#pragma unroll
        for (int k = 0; k < 4; k++) {
            int j = j0 + k;
            bool m = validi && (j <= i) && (amb[j] != 0) &&
                     (((i - j) < WND) || rowAll || (flag[j] != 0));
            rp[k] = m ? 1.0f : 0.0f;
            cnt += m ? 1u : 0u;
        }
        orow[v4] = r;
    }

#pragma unroll
    for (int o = 16; o; o >>= 1) cnt += __shfl_xor_sync(0xffffffffu, cnt, o);
    __shared__ unsigned int scnt[8];
    if ((t & 31) == 0) scnt[t >> 5] = cnt;
    __syncthreads();
    if (t == 0) {
        unsigned int s = 0;
#pragma unroll
        for (int wn = 0; wn < 8; wn++) s += scnt[wn];
        atomicAdd(&g_count[b], s);
    }
}

// ---------------------------------------------------------------------------
// 5) tail: selected (all true for W>=1) + attention efficiency
// ---------------------------------------------------------------------------
__global__ void tail_kernel(float* __restrict__ out, long long out_size) {
    long long base = (long long)BB * SS * SS;
    int idx = blockIdx.x * blockDim.x + threadIdx.x;
    if (idx < BB * SS && base + idx < out_size)
        out[base + idx] = 1.0f;
    if (idx < BB) {
        long long p = base + (long long)BB * SS + idx;
        if (p < out_size)
            out[p] = (float)g_count[idx] / ((float)SS * (float)SS);
    }
}

extern "C" void kernel_launch(void* const* d_in, const int* in_sizes, int n_in,
                              void* d_out, int out_size) {
    const float* h = (const float*)d_in[0];
    const int* am = (const int*)d_in[1];
    const float* w = (const float*)d_in[2];
    float* out = (float*)d_out;

    // 1) importance scores: one warp per (b,s) row
    {
        int warps = BB * SS;
        int threads = 256;
        int blocks = (warps * 32 + threads - 1) / threads;
        scores_kernel<<<blocks, threads>>>(h, am, w);
    }
    // 2) flags init (random tokens) + counter zeroing
    init_kernel<<<(BB * SS + 255) / 256, 256>>>();
    // 3) top-k global tokens
    topk_kernel<<<BB, 1024>>>();
    // 4) dense mask + connection counts
    {
        dim3 grid(SS, BB);
        mask_kernel<<<grid, 256>>>(am, out);
    }
    // 5) selected + efficiency
    tail_kernel<<<(BB * SS + 255) / 256, 256>>>(out, (long long)out_size);
}

// round 2
// speedup vs baseline: 1.6068x; 1.6068x over previous
#include <cuda_runtime.h>
#include <math_constants.h>

#define BB 4
#define SS 4096
#define DD 1024
#define WND 128
#define KTOP 64
#define RSTRIDE 10
#define RBUDGET 409

// scratch (no allocation allowed in kernel_launch)
__device__ unsigned g_keys[BB * SS];       // flipped-float sort keys
__device__ unsigned char g_flag[BB * SS];  // 1 = global-or-random token
__device__ float g_prefval[BB * SS];       // (flag_j && valid_j) ? 1 : 0
__device__ float g_fvalid[BB * SS];        // valid_j ? 1 : 0

// ---------------------------------------------------------------------------
// 1) scores -> sortable keys; also init random flags + fvalid (fused)
// ---------------------------------------------------------------------------
__global__ void scores_kernel(const float* __restrict__ h,
                              const int* __restrict__ am,
                              const float* __restrict__ w) {
    int gw = (blockIdx.x * blockDim.x + threadIdx.x) >> 5;
    int lane = threadIdx.x & 31;
    if (gw >= BB * SS) return;
    const float4* hv = reinterpret_cast<const float4*>(h + (size_t)gw * DD);
    const float4* wv = reinterpret_cast<const float4*>(w);
    float acc = 0.f;
#pragma unroll 4
    for (int i = lane; i < DD / 4; i += 32) {
        float4 a = hv[i];
        float4 b = wv[i];
        acc += a.x * b.x + a.y * b.y + a.z * b.z + a.w * b.w;
    }
#pragma unroll
    for (int o = 16; o; o >>= 1) acc += __shfl_xor_sync(0xffffffffu, acc, o);
    if (lane == 0) {
        int amv = am[gw];
        float v = amv ? acc : -CUDART_INF_F;
        unsigned k = __float_as_uint(v);
        k = (k & 0x80000000u) ? ~k : (k | 0x80000000u);
        g_keys[gw] = k;
        int s = gw & (SS - 1);
        g_flag[gw] = ((s % RSTRIDE) == 0 && (s / RSTRIDE) < RBUDGET) ? 1 : 0;
        g_fvalid[gw] = amv ? 1.0f : 0.0f;
    }
}

// ---------------------------------------------------------------------------
// 2) radix-select top-64 per batch (one 1024-thread block per batch),
//    then materialize prefval (flags are final after this kernel).
// ---------------------------------------------------------------------------
__global__ void topk_kernel(const int* __restrict__ am) {
    __shared__ unsigned skey[SS];     // 16KB keys
    __shared__ unsigned hist[SS];     // 16KB bins; reused as candidate list
    __shared__ unsigned s_w[32];
    __shared__ int s_T;
    __shared__ unsigned s_above, s_ncand;

    int b = blockIdx.x;
    int t = threadIdx.x;
    int lane = t & 31, wid = t >> 5;

    for (int c = 0; c < 4; c++) {
        int i = t + c * 1024;
        skey[i] = g_keys[b * SS + i];
        hist[i] = 0;
    }
    if (t == 0) s_ncand = 0;
    __syncthreads();

    for (int c = 0; c < 4; c++)
        atomicAdd(&hist[skey[t + c * 1024] >> 20], 1u);
    __syncthreads();

    // suffix scan over 4096 bins: count of keys in bins strictly above
    unsigned sl = hist[4 * t] + hist[4 * t + 1] + hist[4 * t + 2] + hist[4 * t + 3];
    unsigned v = sl;
#pragma unroll
    for (int o = 1; o < 32; o <<= 1) {
        unsigned u = __shfl_down_sync(0xffffffffu, v, o);
        if (lane + o < 32) v += u;
    }
    if (lane == 0) s_w[wid] = v;      // warp suffix total
    __syncthreads();
    if (t < 32) {
        unsigned x = s_w[t], y = x;
#pragma unroll
        for (int o = 1; o < 32; o <<= 1) {
            unsigned u = __shfl_down_sync(0xffffffffu, y, o);
            if (t + o < 32) y += u;
        }
        s_w[t] = y - x;               // suffix-exclusive over warps > t
    }
    __syncthreads();
    unsigned above = (v - sl) + s_w[wid];   // sum over threads > t
    for (int bi = 3; bi >= 0; bi--) {
        unsigned hcur = hist[4 * t + bi];
        if (above < KTOP && above + hcur >= KTOP) {
            s_T = 4 * t + bi;
            s_above = above;
        }
        above += hcur;
    }
    __syncthreads();

    // gather: flag above-threshold keys; collect threshold-bin candidates
    int T = s_T;
    unsigned long long* cand = reinterpret_cast<unsigned long long*>(hist);
    for (int c = 0; c < 4; c++) {
        int i = t + c * 1024;
        unsigned k = skey[i];
        int bin = (int)(k >> 20);
        if (bin > T) {
            g_flag[b * SS + i] = 1;
        } else if (bin == T) {
            unsigned p = atomicAdd(&s_ncand, 1u);
            if (p < 2048)
                cand[p] = ((unsigned long long)k << 32) |
                          (unsigned long long)(0xFFFFFFFFu - (unsigned)i);
        }
    }
    __syncthreads();

    // pick remaining r = K - above from candidates (value desc, index asc)
    if (t < 32) {
        int n = (int)min(s_ncand, 2048u);
        int r = KTOP - (int)s_above;
        for (int it = 0; it < r; it++) {
            unsigned long long best = 0ull;
            for (int idx = lane; idx < n; idx += 32) {
                unsigned long long c2 = cand[idx];
                if (c2 > best) best = c2;
            }
#pragma unroll
            for (int o = 16; o; o >>= 1) {
                unsigned long long u = __shfl_xor_sync(0xffffffffu, best, o);
                if (u > best) best = u;
            }
            if (lane == 0) {
                unsigned sel = 0xFFFFFFFFu - (unsigned)(best & 0xFFFFFFFFull);
                g_flag[b * SS + sel] = 1;
            }
            for (int idx = lane; idx < n; idx += 32)
                if (cand[idx] == best) cand[idx] = 0ull;
            __syncwarp();
        }
    }
    __syncthreads();

    // materialize prefval (flags final)
    for (int c = 0; c < 4; c++) {
        int i = t + c * 1024;
        bool fl = g_flag[b * SS + i] != 0;
        bool va = am[b * SS + i] != 0;
        g_prefval[b * SS + i] = (fl && va) ? 1.0f : 0.0f;
    }
}

// ---------------------------------------------------------------------------
// 3) mask write: pure segmented streaming stores
//    row i: [0,lim0) -> prefval (or fvalid if row global), [lim0,i] -> fvalid,
//    (i,SS) -> 0
// ---------------------------------------------------------------------------
__global__ void mask_kernel(const int* __restrict__ am,
                            float* __restrict__ out) {
    int i = blockIdx.x;
    int b = blockIdx.y;
    int t = threadIdx.x;
    bool validi = am[b * SS + i] != 0;
    bool rowAll = g_flag[b * SS + i] != 0;
    const float4* pv = reinterpret_cast<const float4*>(
        (rowAll ? g_fvalid : g_prefval) + b * SS);
    const float4* fv = reinterpret_cast<const float4*>(g_fvalid + b * SS);
    float4* orow = reinterpret_cast<float4*>(out + ((size_t)b * SS + i) * SS);
    int lim0 = i - (WND - 1);
    if (lim0 < 0) lim0 = 0;
    const float4 zero4 = make_float4(0.f, 0.f, 0.f, 0.f);

#pragma unroll
    for (int q = 0; q < 4; q++) {
        int v4 = t + q * 256;
        int j0 = v4 * 4;
        float4 r;
        if (!validi || j0 > i) {
            r = zero4;
        } else if (j0 + 3 < lim0) {
            r = pv[v4];
        } else if (j0 >= lim0 && j0 + 3 <= i) {
            r = fv[v4];
        } else {
            float4 p = pv[v4];
            float4 f = fv[v4];
            float* rp = reinterpret_cast<float*>(&r);
            const float* pp = reinterpret_cast<const float*>(&p);
            const float* fp = reinterpret_cast<const float*>(&f);
#pragma unroll
            for (int k2 = 0; k2 < 4; k2++) {
                int j = j0 + k2;
                rp[k2] = (j > i) ? 0.f : ((j >= lim0) ? fp[k2] : pp[k2]);
            }
        }
        __stcs(&orow[v4], r);
    }
}

// ---------------------------------------------------------------------------
// 4) tail: selected (all true) + analytic per-batch connection count via
//    packed prefix sums of (valid, flag&valid). One block per batch.
// ---------------------------------------------------------------------------
__global__ void tail_kernel(const int* __restrict__ am,
                            float* __restrict__ out, long long out_size) {
    __shared__ unsigned P[SS];   // packed inclusive prefix: low16=valid, high16=flag&valid
    __shared__ unsigned wsum[32];
    int b = blockIdx.x;
    int t = threadIdx.x;
    int lane = t & 31, wid = t >> 5;

    unsigned loc[4];
    unsigned run = 0;
#pragma unroll
    for (int k = 0; k < 4; k++) {
        int j = t * 4 + k;
        unsigned va = (am[b * SS + j] != 0) ? 1u : 0u;
        unsigned fl = (g_flag[b * SS + j] != 0) ? va : 0u;
        run += va + (fl << 16);
        loc[k] = run;
    }
    unsigned v = run;
#pragma unroll
    for (int o = 1; o < 32; o <<= 1) {
        unsigned u = __shfl_up_sync(0xffffffffu, v, o);
        if (lane >= o) v += u;
    }
    if (lane == 31) wsum[wid] = v;
    __syncthreads();
    if (t < 32) {
        unsigned x = wsum[t], y = x;
#pragma unroll
        for (int o = 1; o < 32; o <<= 1) {
            unsigned u = __shfl_up_sync(0xffffffffu, y, o);
            if (t >= o) y += u;
        }
        wsum[t] = y - x;   // exclusive over warps before
    }
    __syncthreads();
    unsigned off = wsum[wid] + (v - run);   // prefix of threads before this one
#pragma unroll
    for (int k = 0; k < 4; k++) P[t * 4 + k] = off + loc[k];
    __syncthreads();

    // per-row counts
    unsigned total = 0;
#pragma unroll
    for (int k = 0; k < 4; k++) {
        int i = t * 4 + k;
        if (am[b * SS + i] != 0) {
            int lim0 = i - (WND - 1);
            if (lim0 < 0) lim0 = 0;
            unsigned Pi = P[i];
            unsigned Plim = lim0 ? P[lim0 - 1] : 0u;
            unsigned nv_win = (Pi & 0xFFFFu) - (Plim & 0xFFFFu);
            unsigned cnt = nv_win +
                ((g_flag[b * SS + i] != 0) ? (Plim & 0xFFFFu) : (Plim >> 16));
            total += cnt;
        }
    }
#pragma unroll
    for (int o = 16; o; o >>= 1) total += __shfl_xor_sync(0xffffffffu, total, o);
    if (lane == 0) wsum[wid] = total;
    __syncthreads();

    // selected region: all true
    long long base = (long long)BB * SS * SS;
#pragma unroll
    for (int k = 0; k < 4; k++) {
        long long p = base + (long long)b * SS + t * 4 + k;
        if (p < out_size) out[p] = 1.0f;
    }
    if (t == 0) {
        unsigned s = 0;
#pragma unroll
        for (int wn = 0; wn < 32; wn++) s += wsum[wn];
        long long p = base + (long long)BB * SS + b;
        if (p < out_size)
            out[p] = (float)s / ((float)SS * (float)SS);
    }
}

extern "C" void kernel_launch(void* const* d_in, const int* in_sizes, int n_in,
                              void* d_out, int out_size) {
    const float* h = (const float*)d_in[0];
    const int* am = (const int*)d_in[1];
    const float* w = (const float*)d_in[2];
    float* out = (float*)d_out;

    {   // 1) scores + random flags + fvalid
        int warps = BB * SS;
        int threads = 256;
        int blocks = (warps * 32 + threads - 1) / threads;
        scores_kernel<<<blocks, threads>>>(h, am, w);
    }
    // 2) radix-select top-k + prefval
    topk_kernel<<<BB, 1024>>>(am);
    // 3) dense mask (pure stores)
    {
        dim3 grid(SS, BB);
        mask_kernel<<<grid, 256>>>(am, out);
    }
    // 4) selected + efficiency
    tail_kernel<<<BB, 1024>>>(am, out, (long long)out_size);
}

// round 3
// speedup vs baseline: 1.6652x; 1.0364x over previous
#include <cuda_runtime.h>
#include <math_constants.h>

#define BB 4
#define SS 4096
#define DD 1024
#define WND 128
#define KTOP 64
#define RSTRIDE 10
#define RBUDGET 409

// scratch (no allocation allowed in kernel_launch)
__device__ unsigned g_keys[BB * SS];       // flipped-float sort keys
__device__ unsigned char g_flag[BB * SS];  // 1 = global-or-random token
__device__ float g_prefval[BB * SS];       // (flag_j && valid_j) ? 1 : 0
__device__ float g_fvalid[BB * SS];        // valid_j ? 1 : 0

// ---------------------------------------------------------------------------
// 1) scores -> sortable keys; also init random flags + fvalid (fused)
// ---------------------------------------------------------------------------
__global__ void scores_kernel(const float* __restrict__ h,
                              const int* __restrict__ am,
                              const float* __restrict__ w) {
    int gw = (blockIdx.x * blockDim.x + threadIdx.x) >> 5;
    int lane = threadIdx.x & 31;
    if (gw >= BB * SS) return;
    const float4* hv = reinterpret_cast<const float4*>(h + (size_t)gw * DD);
    const float4* wv = reinterpret_cast<const float4*>(w);
    float acc = 0.f;
#pragma unroll 4
    for (int i = lane; i < DD / 4; i += 32) {
        float4 a = hv[i];
        float4 b = wv[i];
        acc += a.x * b.x + a.y * b.y + a.z * b.z + a.w * b.w;
    }
#pragma unroll
    for (int o = 16; o; o >>= 1) acc += __shfl_xor_sync(0xffffffffu, acc, o);
    if (lane == 0) {
        int amv = am[gw];
        float v = amv ? acc : -CUDART_INF_F;
        unsigned k = __float_as_uint(v);
        k = (k & 0x80000000u) ? ~k : (k | 0x80000000u);
        g_keys[gw] = k;
        int s = gw & (SS - 1);
        g_flag[gw] = ((s % RSTRIDE) == 0 && (s / RSTRIDE) < RBUDGET) ? 1 : 0;
        g_fvalid[gw] = amv ? 1.0f : 0.0f;
    }
}

// ---------------------------------------------------------------------------
// 2) fused: radix-select top-64 per batch  +  prefval materialization
//    +  analytic connection count  +  selected/efficiency outputs.
//    One 1024-thread block per batch.
// ---------------------------------------------------------------------------
__global__ void topk_tail_kernel(const int* __restrict__ am,
                                 float* __restrict__ out,
                                 long long out_size) {
    __shared__ unsigned skey[SS];     // 16KB keys; later reused as prefix P
    __shared__ unsigned hist[SS];     // 16KB bins; reused as candidate list
    __shared__ unsigned s_w[32];
    __shared__ int s_T;
    __shared__ unsigned s_above, s_ncand;

    int b = blockIdx.x;
    int t = threadIdx.x;
    int lane = t & 31, wid = t >> 5;

    for (int c = 0; c < 4; c++) {
        int i = t + c * 1024;
        skey[i] = g_keys[b * SS + i];
        hist[i] = 0;
    }
    if (t == 0) s_ncand = 0;
    __syncthreads();

    for (int c = 0; c < 4; c++)
        atomicAdd(&hist[skey[t + c * 1024] >> 20], 1u);
    __syncthreads();

    // suffix scan over 4096 bins: count of keys in bins strictly above
    unsigned sl = hist[4 * t] + hist[4 * t + 1] + hist[4 * t + 2] + hist[4 * t + 3];
    unsigned v = sl;
#pragma unroll
    for (int o = 1; o < 32; o <<= 1) {
        unsigned u = __shfl_down_sync(0xffffffffu, v, o);
        if (lane + o < 32) v += u;
    }
    if (lane == 0) s_w[wid] = v;      // warp suffix total
    __syncthreads();
    if (t < 32) {
        unsigned x = s_w[t], y = x;
#pragma unroll
        for (int o = 1; o < 32; o <<= 1) {
            unsigned u = __shfl_down_sync(0xffffffffu, y, o);
            if (t + o < 32) y += u;
        }
        s_w[t] = y - x;               // suffix-exclusive over warps > t
    }
    __syncthreads();
    unsigned above = (v - sl) + s_w[wid];   // sum over threads > t
    for (int bi = 3; bi >= 0; bi--) {
        unsigned hcur = hist[4 * t + bi];
        if (above < KTOP && above + hcur >= KTOP) {
            s_T = 4 * t + bi;
            s_above = above;
        }
        above += hcur;
    }
    __syncthreads();

    // gather: flag above-threshold keys; collect threshold-bin candidates
    int T = s_T;
    unsigned long long* cand = reinterpret_cast<unsigned long long*>(hist);
    for (int c = 0; c < 4; c++) {
        int i = t + c * 1024;
        unsigned k = skey[i];
        int bin = (int)(k >> 20);
        if (bin > T) {
            g_flag[b * SS + i] = 1;
        } else if (bin == T) {
            unsigned p = atomicAdd(&s_ncand, 1u);
            if (p < 2048)
                cand[p] = ((unsigned long long)k << 32) |
                          (unsigned long long)(0xFFFFFFFFu - (unsigned)i);
        }
    }
    __syncthreads();

    // pick remaining r = K - above from candidates (value desc, index asc)
    if (t < 32) {
        int n = (int)min(s_ncand, 2048u);
        int r = KTOP - (int)s_above;
        for (int it = 0; it < r; it++) {
            unsigned long long best = 0ull;
            for (int idx = lane; idx < n; idx += 32) {
                unsigned long long c2 = cand[idx];
                if (c2 > best) best = c2;
            }
#pragma unroll
            for (int o = 16; o; o >>= 1) {
                unsigned long long u = __shfl_xor_sync(0xffffffffu, best, o);
                if (u > best) best = u;
            }
            if (lane == 0) {
                unsigned sel = 0xFFFFFFFFu - (unsigned)(best & 0xFFFFFFFFull);
                g_flag[b * SS + sel] = 1;
            }
            for (int idx = lane; idx < n; idx += 32)
                if (cand[idx] == best) cand[idx] = 0ull;
            __syncwarp();
        }
    }
    __syncthreads();   // flags final + global writes visible to block

    // ---- materialize prefval + gather per-thread valid/flag bits ----
    unsigned va4[4], fl4[4];
#pragma unroll
    for (int k = 0; k < 4; k++) {
        int j = t * 4 + k;
        unsigned va = (am[b * SS + j] != 0) ? 1u : 0u;
        unsigned fl = (g_flag[b * SS + j] != 0) ? 1u : 0u;
        va4[k] = va;
        fl4[k] = fl & va;
        g_prefval[b * SS + j] = (fl & va) ? 1.0f : 0.0f;
    }
    // also prefval for the 3 other chunks this thread covered in load phase?
    // (indexing above covers all SS since 1024 threads * 4 = 4096)

    // ---- packed inclusive prefix: low16 = valid, high16 = flag&valid ----
    unsigned* P = skey;               // reuse
    unsigned loc[4];
    unsigned run = 0;
#pragma unroll
    for (int k = 0; k < 4; k++) {
        run += va4[k] + (fl4[k] << 16);
        loc[k] = run;
    }
    unsigned pv = run;
#pragma unroll
    for (int o = 1; o < 32; o <<= 1) {
        unsigned u = __shfl_up_sync(0xffffffffu, pv, o);
        if (lane >= o) pv += u;
    }
    if (lane == 31) s_w[wid] = pv;
    __syncthreads();
    if (t < 32) {
        unsigned x = s_w[t], y = x;
#pragma unroll
        for (int o = 1; o < 32; o <<= 1) {
            unsigned u = __shfl_up_sync(0xffffffffu, y, o);
            if (t >= o) y += u;
        }
        s_w[t] = y - x;   // exclusive over warps before
    }
    __syncthreads();
    unsigned off = s_w[wid] + (pv - run);
#pragma unroll
    for (int k = 0; k < 4; k++) P[t * 4 + k] = off + loc[k];
    __syncthreads();

    // ---- per-row counts ----
    unsigned total = 0;
#pragma unroll
    for (int k = 0; k < 4; k++) {
        int i = t * 4 + k;
        if (va4[k]) {
            int lim0 = i - (WND - 1);
            if (lim0 < 0) lim0 = 0;
            unsigned Pi = P[i];
            unsigned Plim = lim0 ? P[lim0 - 1] : 0u;
            unsigned nv_win = (Pi & 0xFFFFu) - (Plim & 0xFFFFu);
            bool rowg = (g_flag[b * SS + i] != 0);
            total += nv_win + (rowg ? (Plim & 0xFFFFu) : (Plim >> 16));
        }
    }
#pragma unroll
    for (int o = 16; o; o >>= 1) total += __shfl_xor_sync(0xffffffffu, total, o);
    if (lane == 0) s_w[wid] = total;
    __syncthreads();

    // ---- selected region (all true for W>=1) + efficiency ----
    long long base = (long long)BB * SS * SS;
    {
        long long p0 = base + (long long)b * SS + t * 4;
        if (p0 + 3 < out_size) {
            float4 ones = make_float4(1.f, 1.f, 1.f, 1.f);
            *reinterpret_cast<float4*>(out + p0) = ones;
        } else {
#pragma unroll
            for (int k = 0; k < 4; k++)
                if (p0 + k < out_size) out[p0 + k] = 1.0f;
        }
    }
    if (t == 0) {
        unsigned s = 0;
#pragma unroll
        for (int wn = 0; wn < 32; wn++) s += s_w[wn];
        long long p = base + (long long)BB * SS + b;
        if (p < out_size)
            out[p] = (float)s / ((float)SS * (float)SS);
    }
}

// ---------------------------------------------------------------------------
// 3) mask write: pure segmented streaming stores
//    row i: [0,lim0) -> prefval (or fvalid if row global), [lim0,i] -> fvalid,
//    (i,SS) -> 0
// ---------------------------------------------------------------------------
__global__ void mask_kernel(const int* __restrict__ am,
                            float* __restrict__ out) {
    int i = blockIdx.x;
    int b = blockIdx.y;
    int t = threadIdx.x;
    bool validi = am[b * SS + i] != 0;
    bool rowAll = g_flag[b * SS + i] != 0;
    const float4* pv = reinterpret_cast<const float4*>(
        (rowAll ? g_fvalid : g_prefval) + b * SS);
    const float4* fv = reinterpret_cast<const float4*>(g_fvalid + b * SS);
    float4* orow = reinterpret_cast<float4*>(out + ((size_t)b * SS + i) * SS);
    int lim0 = i - (WND - 1);
    if (lim0 < 0) lim0 = 0;
    const float4 zero4 = make_float4(0.f, 0.f, 0.f, 0.f);

#pragma unroll
    for (int q = 0; q < 4; q++) {
        int v4 = t + q * 256;
        int j0 = v4 * 4;
        float4 r;
        if (!validi || j0 > i) {
            r = zero4;
        } else if (j0 + 3 < lim0) {
            r = pv[v4];
        } else if (j0 >= lim0 && j0 + 3 <= i) {
            r = fv[v4];
        } else {
            float4 p = pv[v4];
            float4 f = fv[v4];
            float* rp = reinterpret_cast<float*>(&r);
            const float* pp = reinterpret_cast<const float*>(&p);
            const float* fp = reinterpret_cast<const float*>(&f);
#pragma unroll
            for (int k2 = 0; k2 < 4; k2++) {
                int j = j0 + k2;
                rp[k2] = (j > i) ? 0.f : ((j >= lim0) ? fp[k2] : pp[k2]);
            }
        }
        __stcs(&orow[v4], r);
    }
}

extern "C" void kernel_launch(void* const* d_in, const int* in_sizes, int n_in,
                              void* d_out, int out_size) {
    const float* h = (const float*)d_in[0];
    const int* am = (const int*)d_in[1];
    const float* w = (const float*)d_in[2];
    float* out = (float*)d_out;

    {   // 1) scores + random flags + fvalid
        int warps = BB * SS;
        int threads = 256;
        int blocks = (warps * 32 + threads - 1) / threads;
        scores_kernel<<<blocks, threads>>>(h, am, w);
    }
    // 2) radix-select top-k + prefval + counts + selected/efficiency
    topk_tail_kernel<<<BB, 1024>>>(am, out, (long long)out_size);
    // 3) dense mask (pure stores)
    {
        dim3 grid(SS, BB);
        mask_kernel<<<grid, 256>>>(am, out);
    }
}